// round 9
// baseline (speedup 1.0000x reference)
#include <cuda_runtime.h>
#include <cuda_fp16.h>
#include <cstdint>

// ---------------- problem constants ----------------
#define N_AG 2048
#define T_K 16
#define D_F 10
#define E_F 128
#define H_F 512
#define M3 (E_F * D_F)      // 1280
#define ND (N_AG * D_F)
#define NPTS 60
#define NE (N_AG * E_F)

// ---------------- scratch ----------------
__device__ float g_M[T_K * ND];
__device__ float g_dX[NPTS * ND];
__device__ float g_zbuf[2 * NE];      // step-parity z buffers (fp32)
__device__ float g_ks[4 * NE];        // per-stage einsum accumulators
__device__ float g_b3p[M3];

#define H16A __device__ __align__(16) __half
H16A g_y0[N_AG * H_F];
H16A g_y1[N_AG * H_F];
H16A g_y2[N_AG * H_F];
H16A g_W0[H_F * E_F];
H16A g_W1[H_F * H_F];
H16A g_W2[H_F * H_F];
H16A g_W3[M3 * H_F];               // rows permuted: dst row = d*128+e

// ---------------- helpers ----------------
__device__ __forceinline__ uint32_t smem_u32(const void* p) {
    uint32_t a;
    asm("{ .reg .u64 t; cvta.to.shared.u64 t, %1; cvt.u32.u64 %0, t; }" : "=r"(a) : "l"(p));
    return a;
}
__device__ __forceinline__ void cp16(uint32_t s, const void* g) {
    asm volatile("cp.async.cg.shared.global [%0], [%1], 16;" :: "r"(s), "l"(g));
}
__device__ __forceinline__ void ldsm4(uint32_t& r0, uint32_t& r1, uint32_t& r2, uint32_t& r3,
                                      uint32_t a) {
    asm volatile("ldmatrix.sync.aligned.m8n8.x4.shared.b16 {%0,%1,%2,%3}, [%4];"
                 : "=r"(r0), "=r"(r1), "=r"(r2), "=r"(r3) : "r"(a));
}
__device__ __forceinline__ void mma16816(float& c0, float& c1, float& c2, float& c3,
                                         uint32_t a0, uint32_t a1, uint32_t a2, uint32_t a3,
                                         uint32_t b0, uint32_t b1) {
    asm volatile("mma.sync.aligned.m16n8k16.row.col.f32.f16.f16.f32 "
                 "{%0,%1,%2,%3},{%4,%5,%6,%7},{%8,%9},{%0,%1,%2,%3};"
                 : "+f"(c0), "+f"(c1), "+f"(c2), "+f"(c3)
                 : "r"(a0), "r"(a1), "r"(a2), "r"(a3), "r"(b0), "r"(b1));
}
__device__ __forceinline__ float fast_tanh(float x) {
    x = fminf(fmaxf(x, -15.f), 15.f);
    float e = __expf(-2.f * x);
    return (1.f - e) * __frcp_rn(1.f + e);
}

// smem: STRIDE 72 halves (144 B rows) -> conflict-free ldmatrix & cp.async
#define STRIDE 72
#define TILE_A 18432          // 128 x 72 halves x 2B
#define TILE_B 9216           // 64 x 72 halves x 2B
#define BUF_B (TILE_A + TILE_B)   // 27648 per double-buffer stage (L1/L2/L3)
#define SMEM_BYTES 55296

// ================= L1/L2 GEMM: C = relu(A @ W^T + b), fp16 out; optional k-zero ======
__global__ void __launch_bounds__(256) mma_gemm_relu(
    const __half* __restrict__ A, const __half* __restrict__ Bw,
    const float* __restrict__ bias, __half* __restrict__ C,
    float* kz, int K, int Mout)
{
    extern __shared__ char smem[];
    const uint32_t sb = smem_u32(smem);
    const int tid = threadIdx.x, wid = tid >> 5, lid = tid & 31;
    const int rowBase = blockIdx.y * 128;
    const int colBase = blockIdx.x * 64;
    const int warpM = (wid & 3) * 32;
    const int warpN = (wid >> 2) * 32;
    const int grp = lid >> 2, q = lid & 3;

    // zero the einsum accumulator slice for this stage (only L1 passes kz)
    if (kz) {
        float4 zz = make_float4(0.f, 0.f, 0.f, 0.f);
        float* p = kz + (size_t)rowBase * 128 + blockIdx.x * 2048 + tid * 8;
        *(float4*)p = zz; *(float4*)(p + 4) = zz;
    }

    // cp.async mapping (BK=64)
    const int ar  = tid >> 1;            // A row 0..127
    const int acb = (tid & 1) * 32;      // half offset
    const int br2 = tid >> 2;            // B row 0..63
    const int bcb = (tid & 3) * 16;

    const __half* gA = A  + (size_t)(rowBase + ar) * K + acb;
    const __half* gB = Bw + (size_t)(colBase + br2) * K + bcb;
    const uint32_t sA = sb + (ar * STRIDE + acb) * 2;
    const uint32_t sB = sb + TILE_A + (br2 * STRIDE + bcb) * 2;

    // ldmatrix lane addressing
    const int sel  = lid >> 3;
    const int lrow = (sel & 1) * 8 + (lid & 7);
    const int lcol = (sel >> 1) * 8;
    const uint32_t aoff0 = ((warpM + lrow) * STRIDE + lcol) * 2;
    const uint32_t aoff1 = ((warpM + 16 + lrow) * STRIDE + lcol) * 2;
    const uint32_t boff0 = ((warpN + lrow) * STRIDE + lcol) * 2;
    const uint32_t boff1 = ((warpN + 16 + lrow) * STRIDE + lcol) * 2;

    float c[2][4][4];
#pragma unroll
    for (int mi = 0; mi < 2; mi++)
#pragma unroll
        for (int ni = 0; ni < 4; ni++)
#pragma unroll
            for (int r = 0; r < 4; r++) c[mi][ni][r] = 0.f;

    const int NK = K >> 6;

    // prologue: tile 0 -> buffer 0
#pragma unroll
    for (int j = 0; j < 4; j++) cp16(sA + j * 16, gA + j * 8);
    cp16(sB, gB); cp16(sB + 16, gB + 8);
    asm volatile("cp.async.commit_group;");

    for (int kt = 0; kt < NK; kt++) {
        if (kt + 1 < NK) {
            const int k0 = (kt + 1) << 6;
            const uint32_t bo = ((kt + 1) & 1) * BUF_B;
#pragma unroll
            for (int j = 0; j < 4; j++) cp16(sA + bo + j * 16, gA + k0 + j * 8);
            cp16(sB + bo, gB + k0); cp16(sB + bo + 16, gB + k0 + 8);
        }
        asm volatile("cp.async.commit_group;");
        asm volatile("cp.async.wait_group 1;");
        __syncthreads();

        const uint32_t aBase = sb + (kt & 1) * BUF_B;
#pragma unroll
        for (int kk = 0; kk < 64; kk += 16) {
            const uint32_t kb = kk * 2;
            uint32_t a[2][4], b[4][2];
            ldsm4(a[0][0], a[0][1], a[0][2], a[0][3], aBase + aoff0 + kb);
            ldsm4(a[1][0], a[1][1], a[1][2], a[1][3], aBase + aoff1 + kb);
            ldsm4(b[0][0], b[1][0], b[0][1], b[1][1], aBase + TILE_A + boff0 + kb);
            ldsm4(b[2][0], b[3][0], b[2][1], b[3][1], aBase + TILE_A + boff1 + kb);
#pragma unroll
            for (int mi = 0; mi < 2; mi++)
#pragma unroll
                for (int ni = 0; ni < 4; ni++)
                    mma16816(c[mi][ni][0], c[mi][ni][1], c[mi][ni][2], c[mi][ni][3],
                             a[mi][0], a[mi][1], a[mi][2], a[mi][3],
                             b[ni][0], b[ni][1]);
        }
        __syncthreads();
    }

#pragma unroll
    for (int ni = 0; ni < 4; ni++) {
        const int col = colBase + warpN + ni * 8 + q * 2;
        const float bv0 = bias[col], bv1 = bias[col + 1];
#pragma unroll
        for (int mi = 0; mi < 2; mi++) {
            const int row0 = rowBase + warpM + mi * 16 + grp;
            float v00 = fmaxf(c[mi][ni][0] + bv0, 0.f), v01 = fmaxf(c[mi][ni][1] + bv1, 0.f);
            float v10 = fmaxf(c[mi][ni][2] + bv0, 0.f), v11 = fmaxf(c[mi][ni][3] + bv1, 0.f);
            __half2 H0 = __floats2half2_rn(v00, v01);
            __half2 H1 = __floats2half2_rn(v10, v11);
            *(uint32_t*)(C + (size_t)row0 * Mout + col) = *(uint32_t*)&H0;
            *(uint32_t*)(C + (size_t)(row0 + 8) * Mout + col) = *(uint32_t*)&H1;
        }
    }
}

// ================= L3 GEMM: tanh + fused einsum (atomicAdd into ks) ==================
__global__ void __launch_bounds__(256) mma_gemm_vf(
    const __half* __restrict__ A, const __half* __restrict__ Bw,
    const float* __restrict__ bias, const float* __restrict__ dx,
    float* __restrict__ ks, int K)
{
    extern __shared__ char smem[];
    const uint32_t sb = smem_u32(smem);
    const int tid = threadIdx.x, wid = tid >> 5, lid = tid & 31;
    const int rowBase = blockIdx.y * 128;
    const int colBase = blockIdx.x * 64;
    const int warpM = (wid & 3) * 32;
    const int warpN = (wid >> 2) * 32;
    const int grp = lid >> 2, q = lid & 3;
    const int d = blockIdx.x >> 1;       // permuted layout: 64-col tile = single d

    const int ar  = tid >> 1;
    const int acb = (tid & 1) * 32;
    const int br2 = tid >> 2;
    const int bcb = (tid & 3) * 16;

    const __half* gA = A  + (size_t)(rowBase + ar) * K + acb;
    const __half* gB = Bw + (size_t)(colBase + br2) * K + bcb;
    const uint32_t sA = sb + (ar * STRIDE + acb) * 2;
    const uint32_t sB = sb + TILE_A + (br2 * STRIDE + bcb) * 2;

    const int sel  = lid >> 3;
    const int lrow = (sel & 1) * 8 + (lid & 7);
    const int lcol = (sel >> 1) * 8;
    const uint32_t aoff0 = ((warpM + lrow) * STRIDE + lcol) * 2;
    const uint32_t aoff1 = ((warpM + 16 + lrow) * STRIDE + lcol) * 2;
    const uint32_t boff0 = ((warpN + lrow) * STRIDE + lcol) * 2;
    const uint32_t boff1 = ((warpN + 16 + lrow) * STRIDE + lcol) * 2;

    float c[2][4][4];
#pragma unroll
    for (int mi = 0; mi < 2; mi++)
#pragma unroll
        for (int ni = 0; ni < 4; ni++)
#pragma unroll
            for (int r = 0; r < 4; r++) c[mi][ni][r] = 0.f;

    const int NK = K >> 6;
#pragma unroll
    for (int j = 0; j < 4; j++) cp16(sA + j * 16, gA + j * 8);
    cp16(sB, gB); cp16(sB + 16, gB + 8);
    asm volatile("cp.async.commit_group;");

    for (int kt = 0; kt < NK; kt++) {
        if (kt + 1 < NK) {
            const int k0 = (kt + 1) << 6;
            const uint32_t bo = ((kt + 1) & 1) * BUF_B;
#pragma unroll
            for (int j = 0; j < 4; j++) cp16(sA + bo + j * 16, gA + k0 + j * 8);
            cp16(sB + bo, gB + k0); cp16(sB + bo + 16, gB + k0 + 8);
        }
        asm volatile("cp.async.commit_group;");
        asm volatile("cp.async.wait_group 1;");
        __syncthreads();

        const uint32_t aBase = sb + (kt & 1) * BUF_B;
#pragma unroll
        for (int kk = 0; kk < 64; kk += 16) {
            const uint32_t kb = kk * 2;
            uint32_t a[2][4], b[4][2];
            ldsm4(a[0][0], a[0][1], a[0][2], a[0][3], aBase + aoff0 + kb);
            ldsm4(a[1][0], a[1][1], a[1][2], a[1][3], aBase + aoff1 + kb);
            ldsm4(b[0][0], b[1][0], b[0][1], b[1][1], aBase + TILE_A + boff0 + kb);
            ldsm4(b[2][0], b[3][0], b[2][1], b[3][1], aBase + TILE_A + boff1 + kb);
#pragma unroll
            for (int mi = 0; mi < 2; mi++)
#pragma unroll
                for (int ni = 0; ni < 4; ni++)
                    mma16816(c[mi][ni][0], c[mi][ni][1], c[mi][ni][2], c[mi][ni][3],
                             a[mi][0], a[mi][1], a[mi][2], a[mi][3],
                             b[ni][0], b[ni][1]);
        }
        __syncthreads();
    }

    // epilogue: tanh, multiply by dX[n,d], atomically accumulate into ks[n,e]
#pragma unroll
    for (int mi = 0; mi < 2; mi++) {
        const int row0 = rowBase + warpM + mi * 16 + grp;
        const float dx0 = dx[row0 * D_F + d];
        const float dx1 = dx[(row0 + 8) * D_F + d];
        float* k0p = ks + (size_t)row0 * 128;
        float* k1p = ks + (size_t)(row0 + 8) * 128;
#pragma unroll
        for (int ni = 0; ni < 4; ni++) {
            const int col = colBase + warpN + ni * 8 + q * 2;
            const int e = col & 127;
            const float bv0 = bias[col], bv1 = bias[col + 1];
            atomicAdd(k0p + e,     fast_tanh(c[mi][ni][0] + bv0) * dx0);
            atomicAdd(k0p + e + 1, fast_tanh(c[mi][ni][1] + bv1) * dx0);
            atomicAdd(k1p + e,     fast_tanh(c[mi][ni][2] + bv0) * dx1);
            atomicAdd(k1p + e + 1, fast_tanh(c[mi][ni][3] + bv1) * dx1);
        }
    }
}

// ================= L0: fused RK-combine + GEMM (K=128) ==============================
__global__ void __launch_bounds__(256) l0_gemm(
    const float* __restrict__ zprev, float* __restrict__ zcur,
    const float* __restrict__ t, int k, int stage,
    const __half* __restrict__ Bw, const float* __restrict__ bias,
    __half* __restrict__ C,
    const float* __restrict__ ks0, const float* __restrict__ ks1,
    const float* __restrict__ ks2, const float* __restrict__ ks3)
{
    extern __shared__ char smem[];
    const uint32_t sb = smem_u32(smem);
    const int tid = threadIdx.x, wid = tid >> 5, lid = tid & 31;
    const int rowBase = blockIdx.y * 128;
    const int colBase = blockIdx.x * 64;
    const int warpM = (wid & 3) * 32;
    const int warpN = (wid >> 2) * 32;
    const int grp = lid >> 2, q = lid & 3;

    // kick off both B tiles (K=128 -> 2 tiles of 64) while we compute zin
    {
        const int br2 = tid >> 2;
        const int bcb = (tid & 3) * 16;
        const __half* gB = Bw + (size_t)(colBase + br2) * 128 + bcb;
#pragma unroll
        for (int kt = 0; kt < 2; kt++) {
            uint32_t sB = sb + 2 * TILE_A + kt * TILE_B + (br2 * STRIDE + bcb) * 2;
            cp16(sB, gB + kt * 64); cp16(sB + 16, gB + kt * 64 + 8);
        }
        asm volatile("cp.async.commit_group;");
    }

    // compute zin rows (fp32) -> fp16 -> smem A tiles
    {
        const float h  = t[k + 1] - t[k];
        const float hp = (k > 0) ? (t[k] - t[k - 1]) : 0.f;
        const size_t base = (size_t)rowBase * 128;
        const float* zsrc = (stage == 0) ? zprev : zcur;
#pragma unroll 4
        for (int i = 0; i < 16; i++) {
            const int j = i * 256 + tid;
            float4 zv = *(const float4*)(zsrc + base + (size_t)j * 4);
            float4 zin;
            if (stage == 0) {
                if (k > 0) {
                    float4 a = *(const float4*)(ks0 + base + j * 4);
                    float4 b = *(const float4*)(ks1 + base + j * 4);
                    float4 cc = *(const float4*)(ks2 + base + j * 4);
                    float4 dd = *(const float4*)(ks3 + base + j * 4);
                    zin.x = zv.x + hp * (a.x + 3.f * (b.x + cc.x) + dd.x) * 0.125f;
                    zin.y = zv.y + hp * (a.y + 3.f * (b.y + cc.y) + dd.y) * 0.125f;
                    zin.z = zv.z + hp * (a.z + 3.f * (b.z + cc.z) + dd.z) * 0.125f;
                    zin.w = zv.w + hp * (a.w + 3.f * (b.w + cc.w) + dd.w) * 0.125f;
                    *(float4*)(zcur + base + (size_t)j * 4) = zin;
                } else zin = zv;
            } else if (stage == 1) {
                float4 a = *(const float4*)(ks0 + base + j * 4);
                zin.x = zv.x + h * a.x / 3.f; zin.y = zv.y + h * a.y / 3.f;
                zin.z = zv.z + h * a.z / 3.f; zin.w = zv.w + h * a.w / 3.f;
            } else if (stage == 2) {
                float4 a = *(const float4*)(ks0 + base + j * 4);
                float4 b = *(const float4*)(ks1 + base + j * 4);
                zin.x = zv.x + h * (b.x - a.x / 3.f); zin.y = zv.y + h * (b.y - a.y / 3.f);
                zin.z = zv.z + h * (b.z - a.z / 3.f); zin.w = zv.w + h * (b.w - a.w / 3.f);
            } else {
                float4 a = *(const float4*)(ks0 + base + j * 4);
                float4 b = *(const float4*)(ks1 + base + j * 4);
                float4 cc = *(const float4*)(ks2 + base + j * 4);
                zin.x = zv.x + h * (a.x - b.x + cc.x); zin.y = zv.y + h * (a.y - b.y + cc.y);
                zin.z = zv.z + h * (a.z - b.z + cc.z); zin.w = zv.w + h * (a.w - b.w + cc.w);
            }
            const int row = j >> 5;
            const int colf = (j & 31) * 4;
            const int tile = colf >> 6;
            const int cc2 = colf & 63;
            __half2 h0 = __floats2half2_rn(zin.x, zin.y);
            __half2 h1 = __floats2half2_rn(zin.z, zin.w);
            uint2 v; v.x = *(uint32_t*)&h0; v.y = *(uint32_t*)&h1;
            *(uint2*)(smem + tile * TILE_A + (row * STRIDE + cc2) * 2) = v;
        }
    }
    asm volatile("cp.async.wait_group 0;");
    __syncthreads();

    const int sel  = lid >> 3;
    const int lrow = (sel & 1) * 8 + (lid & 7);
    const int lcol = (sel >> 1) * 8;
    const uint32_t aoff0 = ((warpM + lrow) * STRIDE + lcol) * 2;
    const uint32_t aoff1 = ((warpM + 16 + lrow) * STRIDE + lcol) * 2;
    const uint32_t boff0 = ((warpN + lrow) * STRIDE + lcol) * 2;
    const uint32_t boff1 = ((warpN + 16 + lrow) * STRIDE + lcol) * 2;

    float c[2][4][4];
#pragma unroll
    for (int mi = 0; mi < 2; mi++)
#pragma unroll
        for (int ni = 0; ni < 4; ni++)
#pragma unroll
            for (int r = 0; r < 4; r++) c[mi][ni][r] = 0.f;

#pragma unroll
    for (int kt = 0; kt < 2; kt++) {
        const uint32_t aBase = sb + kt * TILE_A;
        const uint32_t bBase = sb + 2 * TILE_A + kt * TILE_B;
#pragma unroll
        for (int kk = 0; kk < 64; kk += 16) {
            const uint32_t kb = kk * 2;
            uint32_t a[2][4], b[4][2];
            ldsm4(a[0][0], a[0][1], a[0][2], a[0][3], aBase + aoff0 + kb);
            ldsm4(a[1][0], a[1][1], a[1][2], a[1][3], aBase + aoff1 + kb);
            ldsm4(b[0][0], b[1][0], b[0][1], b[1][1], bBase + boff0 + kb);
            ldsm4(b[2][0], b[3][0], b[2][1], b[3][1], bBase + boff1 + kb);
#pragma unroll
            for (int mi = 0; mi < 2; mi++)
#pragma unroll
                for (int ni = 0; ni < 4; ni++)
                    mma16816(c[mi][ni][0], c[mi][ni][1], c[mi][ni][2], c[mi][ni][3],
                             a[mi][0], a[mi][1], a[mi][2], a[mi][3],
                             b[ni][0], b[ni][1]);
        }
    }

#pragma unroll
    for (int ni = 0; ni < 4; ni++) {
        const int col = colBase + warpN + ni * 8 + q * 2;
        const float bv0 = bias[col], bv1 = bias[col + 1];
#pragma unroll
        for (int mi = 0; mi < 2; mi++) {
            const int row0 = rowBase + warpM + mi * 16 + grp;
            float v00 = fmaxf(c[mi][ni][0] + bv0, 0.f), v01 = fmaxf(c[mi][ni][1] + bv1, 0.f);
            float v10 = fmaxf(c[mi][ni][2] + bv0, 0.f), v11 = fmaxf(c[mi][ni][3] + bv1, 0.f);
            __half2 H0 = __floats2half2_rn(v00, v01);
            __half2 H1 = __floats2half2_rn(v10, v11);
            *(uint32_t*)(C + (size_t)row0 * H_F + col) = *(uint32_t*)&H0;
            *(uint32_t*)(C + (size_t)(row0 + 8) * H_F + col) = *(uint32_t*)&H1;
        }
    }
}

// ---------------- weight round to fp16 ----------------
__global__ void wround(const float* __restrict__ s, __half* __restrict__ h, int n) {
    int idx = blockIdx.x * blockDim.x + threadIdx.x;
    if (idx >= n) return;
    h[idx] = __float2half_rn(s[idx]);
}
__global__ void wround_w3(const float* __restrict__ s, __half* __restrict__ h) {
    int idx = blockIdx.x * blockDim.x + threadIdx.x;
    if (idx >= M3 * H_F) return;
    int r = idx >> 9, kk = idx & 511;
    int e = r / D_F, d = r - e * D_F;
    h[(size_t)(d * E_F + e) * H_F + kk] = __float2half_rn(s[idx]);
}
__global__ void b3perm(const float* __restrict__ b3) {
    int idx = blockIdx.x * blockDim.x + threadIdx.x;
    if (idx >= M3) return;
    int e = idx / D_F, d = idx - e * D_F;
    g_b3p[d * E_F + e] = b3[idx];
}

// ---------------- spline ----------------
__global__ void spline_kernel(const float* __restrict__ t, const float* __restrict__ x) {
    int col = blockIdx.x * blockDim.x + threadIdx.x;
    if (col >= ND) return;
    int n = col / D_F, d = col % D_F;
    float tv[T_K];
#pragma unroll
    for (int i = 0; i < T_K; i++) tv[i] = t[i];
    float xv[T_K];
#pragma unroll
    for (int i = 0; i < T_K; i++) xv[i] = x[(n * T_K + i) * D_F + d];
    float h[T_K - 1];
#pragma unroll
    for (int i = 0; i < T_K - 1; i++) h[i] = tv[i + 1] - tv[i];
    float cp[T_K], dp[T_K];
    cp[0] = 0.f; dp[0] = 0.f;
#pragma unroll
    for (int i = 1; i < T_K - 1; i++) {
        float rhs = 6.f * ((xv[i + 1] - xv[i]) / h[i] - (xv[i] - xv[i - 1]) / h[i - 1]);
        float m = 2.f * (h[i - 1] + h[i]) - h[i - 1] * cp[i - 1];
        float inv = 1.f / m;
        cp[i] = h[i] * inv;
        dp[i] = (rhs - h[i - 1] * dp[i - 1]) * inv;
    }
    float Mv[T_K];
    Mv[T_K - 1] = 0.f;
#pragma unroll
    for (int i = T_K - 2; i >= 0; i--) Mv[i] = dp[i] - cp[i] * Mv[i + 1];
#pragma unroll
    for (int i = 0; i < T_K; i++) g_M[i * ND + col] = Mv[i];
}

// ---------------- dX/dt ----------------
__global__ void dx_kernel(const float* __restrict__ t, const float* __restrict__ x) {
    int idx = blockIdx.x * blockDim.x + threadIdx.x;
    if (idx >= NPTS * ND) return;
    int pt = idx / ND, col = idx - pt * ND;
    int n = col / D_F, d = col - n * D_F;
    int k = pt >> 2, j = pt & 3;
    float t0 = t[k], t1 = t[k + 1];
    float hs = t1 - t0;
    float s;
    if (j == 0) s = t0;
    else if (j == 1) s = t0 + hs / 3.0f;
    else if (j == 2) s = t0 + 2.0f * hs / 3.0f;
    else s = t1;
    int cnt = 0;
#pragma unroll
    for (int i = 0; i < T_K; i++) cnt += (t[i] <= s) ? 1 : 0;
    int i = min(max(cnt - 1, 0), T_K - 2);
    float hi = t[i + 1] - t[i];
    float xi  = x[(n * T_K + i) * D_F + d];
    float xi1 = x[(n * T_K + i + 1) * D_F + d];
    float Mi  = g_M[i * ND + col];
    float Mi1 = g_M[(i + 1) * ND + col];
    float u = s - t[i];
    float b = (xi1 - xi) / hi - hi * (2.0f * Mi + Mi1) / 6.0f;
    g_dX[idx] = b + Mi * u + (Mi1 - Mi) * (u * u) / (2.0f * hi);
}

// ---------------- z0 ----------------
__global__ void z0_kernel(const float* __restrict__ x, const float* __restrict__ We,
                          const float* __restrict__ be) {
    int idx = blockIdx.x * blockDim.x + threadIdx.x;
    if (idx >= NE) return;
    int n = idx / E_F, e = idx - n * E_F;
    float acc = be[e];
#pragma unroll
    for (int d = 0; d < D_F; d++) acc += x[n * T_K * D_F + d] * We[e * D_F + d];
    g_zbuf[idx] = acc;
}

// ---------------- output: final RK combine + mask ----------------
__global__ void out_kernel(const float* __restrict__ t, const int* __restrict__ mask,
                           float* __restrict__ out) {
    int idx = blockIdx.x * blockDim.x + threadIdx.x;
    if (idx >= NE) return;
    int n = idx / E_F;
    float h = t[T_K - 1] - t[T_K - 2];
    float z = g_zbuf[idx];   // z for step 14 lives in parity buffer 0
    float zn = z + h * (g_ks[idx] + 3.f * (g_ks[NE + idx] + g_ks[2 * NE + idx])
                        + g_ks[3 * NE + idx]) * 0.125f;
    out[idx] = (mask[n] != 0) ? zn : 0.0f;
}

// ---------------- launcher ----------------
extern "C" void kernel_launch(void* const* d_in, const int* in_sizes, int n_in,
                              void* d_out, int out_size) {
    const float* t  = (const float*)d_in[0];
    const float* x  = (const float*)d_in[1];
    const int*   mask = (const int*)d_in[2];
    const float* We = (const float*)d_in[3];
    const float* be = (const float*)d_in[4];
    const float* W0 = (const float*)d_in[5];
    const float* b0 = (const float*)d_in[6];
    const float* W1 = (const float*)d_in[7];
    const float* b1 = (const float*)d_in[8];
    const float* W2 = (const float*)d_in[9];
    const float* b2 = (const float*)d_in[10];
    const float* W3 = (const float*)d_in[11];
    const float* b3 = (const float*)d_in[12];

    cudaFuncSetAttribute(mma_gemm_relu, cudaFuncAttributeMaxDynamicSharedMemorySize, SMEM_BYTES);
    cudaFuncSetAttribute(mma_gemm_vf,   cudaFuncAttributeMaxDynamicSharedMemorySize, SMEM_BYTES);
    cudaFuncSetAttribute(l0_gemm,       cudaFuncAttributeMaxDynamicSharedMemorySize, SMEM_BYTES);

    __half *y0, *y1, *y2, *W0r, *W1r, *W2r, *W3r;
    float *zb, *ksb, *b3p, *dXp;
    cudaGetSymbolAddress((void**)&y0, g_y0);
    cudaGetSymbolAddress((void**)&y1, g_y1);
    cudaGetSymbolAddress((void**)&y2, g_y2);
    cudaGetSymbolAddress((void**)&W0r, g_W0); cudaGetSymbolAddress((void**)&W1r, g_W1);
    cudaGetSymbolAddress((void**)&W2r, g_W2); cudaGetSymbolAddress((void**)&W3r, g_W3);
    cudaGetSymbolAddress((void**)&zb, g_zbuf);
    cudaGetSymbolAddress((void**)&ksb, g_ks);
    cudaGetSymbolAddress((void**)&b3p, g_b3p);
    cudaGetSymbolAddress((void**)&dXp, g_dX);

    float* ks[4] = {ksb, ksb + NE, ksb + 2 * NE, ksb + 3 * NE};

    wround<<<(H_F * E_F + 255) / 256, 256>>>(W0, W0r, H_F * E_F);
    wround<<<(H_F * H_F + 255) / 256, 256>>>(W1, W1r, H_F * H_F);
    wround<<<(H_F * H_F + 255) / 256, 256>>>(W2, W2r, H_F * H_F);
    wround_w3<<<(M3 * H_F + 255) / 256, 256>>>(W3, W3r);
    b3perm<<<(M3 + 255) / 256, 256>>>(b3);

    spline_kernel<<<(ND + 255) / 256, 256>>>(t, x);
    dx_kernel<<<(NPTS * ND + 255) / 256, 256>>>(t, x);
    z0_kernel<<<(NE + 255) / 256, 256>>>(x, We, be);

    dim3 gH(8, 16);
    dim3 g3(20, 16);

    for (int k = 0; k < T_K - 1; k++) {
        float* zprev = zb + ((k > 0) ? ((k - 1) & 1) : 0) * NE;
        float* zcur  = zb + (k & 1) * NE;
        for (int s = 0; s < 4; s++) {
            l0_gemm<<<gH, 256, SMEM_BYTES>>>(zprev, zcur, t, k, s, W0r, b0, y0,
                                             ks[0], ks[1], ks[2], ks[3]);
            mma_gemm_relu<<<gH, 256, SMEM_BYTES>>>(y0, W1r, b1, y1, ks[s], H_F, H_F);
            mma_gemm_relu<<<gH, 256, SMEM_BYTES>>>(y1, W2r, b2, y2, nullptr, H_F, H_F);
            mma_gemm_vf<<<g3, 256, SMEM_BYTES>>>(y2, W3r, b3p, dXp + (size_t)(k * 4 + s) * ND,
                                                 ks[s], H_F);
        }
    }
    out_kernel<<<(NE + 255) / 256, 256>>>(t, mask, (float*)d_out);
}

// round 10
// speedup vs baseline: 1.1566x; 1.1566x over previous
#include <cuda_runtime.h>
#include <cuda_fp16.h>
#include <cstdint>

// ---------------- problem constants ----------------
#define N_AG 2048
#define T_K 16
#define D_F 10
#define E_F 128
#define H_F 512
#define M3 (E_F * D_F)      // 1280
#define ND (N_AG * D_F)
#define NPTS 60
#define NE (N_AG * E_F)

// ---------------- scratch ----------------
__device__ float g_M[T_K * ND];
__device__ float g_dX[NPTS * ND];
__device__ float g_z[NE];
__device__ float g_k1[NE];
__device__ float g_k2[NE];
__device__ float g_k3[NE];
__device__ float g_y3[N_AG * M3];     // layout [n][d*128+e]
__device__ float g_b3p[M3];

#define H16A __device__ __align__(16) __half
H16A g_zh[NE];
H16A g_zinh[NE];
H16A g_y0[N_AG * H_F];
H16A g_y1[N_AG * H_F];
H16A g_y2[N_AG * H_F];
H16A g_W0[H_F * E_F];
H16A g_W1[H_F * H_F];
H16A g_W2[H_F * H_F];
H16A g_W3[M3 * H_F];               // rows permuted: dst row = d*128+e

// ---------------- helpers ----------------
__device__ __forceinline__ uint32_t smem_u32(const void* p) {
    uint32_t a;
    asm("{ .reg .u64 t; cvta.to.shared.u64 t, %1; cvt.u32.u64 %0, t; }" : "=r"(a) : "l"(p));
    return a;
}
__device__ __forceinline__ void cp16(uint32_t s, const void* g) {
    asm volatile("cp.async.cg.shared.global [%0], [%1], 16;" :: "r"(s), "l"(g));
}
__device__ __forceinline__ void ldsm4(uint32_t& r0, uint32_t& r1, uint32_t& r2, uint32_t& r3,
                                      uint32_t a) {
    asm volatile("ldmatrix.sync.aligned.m8n8.x4.shared.b16 {%0,%1,%2,%3}, [%4];"
                 : "=r"(r0), "=r"(r1), "=r"(r2), "=r"(r3) : "r"(a));
}
__device__ __forceinline__ void mma16816(float& c0, float& c1, float& c2, float& c3,
                                         uint32_t a0, uint32_t a1, uint32_t a2, uint32_t a3,
                                         uint32_t b0, uint32_t b1) {
    asm volatile("mma.sync.aligned.m16n8k16.row.col.f32.f16.f16.f32 "
                 "{%0,%1,%2,%3},{%4,%5,%6,%7},{%8,%9},{%0,%1,%2,%3};"
                 : "+f"(c0), "+f"(c1), "+f"(c2), "+f"(c3)
                 : "r"(a0), "r"(a1), "r"(a2), "r"(a3), "r"(b0), "r"(b1));
}
__device__ __forceinline__ float fast_tanh(float x) {
    x = fminf(fmaxf(x, -15.f), 15.f);
    float e = __expf(-2.f * x);
    return (1.f - e) * __frcp_rn(1.f + e);
}

// smem per stage buffer: STRIDE 40 halves (80 B rows). A 10240 B, B 5120 B.
#define STRIDE 40
#define OFF_A  0
#define OFF_B  10240
#define BUF_B  15360
#define NSTAGE 4
#define SMEM_BYTES (NSTAGE * BUF_B)      // 61440

// ---------------- fp16 HMMA GEMM, 4-stage cp.async pipeline ----------------
// CTA 128x64, BK=32, 8 warps 4(M)x2(N), warp tile 32x32, ldmatrix feeds.
template <int ACT>  // 0: relu + fp16 out; 1: tanh + fp32 out
__global__ void __launch_bounds__(256) mma_gemm(
    const __half* __restrict__ A, const __half* __restrict__ Bw,
    const float* __restrict__ bias,
    __half* __restrict__ Ch, float* __restrict__ Cf, int K, int Mout)
{
    extern __shared__ char smem[];
    const uint32_t sb = smem_u32(smem);
    const int tid = threadIdx.x, wid = tid >> 5, lid = tid & 31;
    const int rowBase = blockIdx.y * 128;
    const int colBase = blockIdx.x * 64;
    const int warpM = (wid & 3) * 32;
    const int warpN = (wid >> 2) * 32;
    const int grp = lid >> 2, q = lid & 3;

    // cp.async mapping (BK=32)
    const int ar  = tid >> 1;            // A row 0..127
    const int acb = (tid & 1) * 16;      // half-offset
    const int br2 = tid >> 2;            // B row 0..63
    const int bcb = (tid & 3) * 8;

    const __half* gA = A  + (size_t)(rowBase + ar) * K + acb;
    const __half* gB = Bw + (size_t)(colBase + br2) * K + bcb;

    const uint32_t sA = sb + OFF_A + (ar * STRIDE + acb) * 2;
    const uint32_t sB = sb + OFF_B + (br2 * STRIDE + bcb) * 2;

    // ldmatrix lane addressing
    const int sel  = lid >> 3;
    const int lrow = (sel & 1) * 8 + (lid & 7);
    const int lcol = (sel >> 1) * 8;
    const uint32_t aoff0 = ((warpM + lrow) * STRIDE + lcol) * 2;
    const uint32_t aoff1 = ((warpM + 16 + lrow) * STRIDE + lcol) * 2;
    const uint32_t boff0 = ((warpN + lrow) * STRIDE + lcol) * 2;
    const uint32_t boff1 = ((warpN + 16 + lrow) * STRIDE + lcol) * 2;

    float c[2][4][4];
#pragma unroll
    for (int mi = 0; mi < 2; mi++)
#pragma unroll
        for (int ni = 0; ni < 4; ni++)
#pragma unroll
            for (int r = 0; r < 4; r++) c[mi][ni][r] = 0.f;

    const int NK = K >> 5;

    // prologue: stage tiles 0..2 (one commit group each)
#pragma unroll
    for (int s = 0; s < NSTAGE - 1; s++) {
        if (s < NK) {
            const int k0 = s << 5;
            const uint32_t bo = s * BUF_B;
            cp16(sA + bo, gA + k0); cp16(sA + bo + 16, gA + k0 + 8);
            cp16(sB + bo, gB + k0);
        }
        asm volatile("cp.async.commit_group;");
    }

    for (int kt = 0; kt < NK; kt++) {
        // tile kt complete when pending groups <= 2
        asm volatile("cp.async.wait_group %0;" :: "n"(NSTAGE - 2));
        __syncthreads();

        // issue tile kt+3 into buffer (kt+3)&3 (its readers finished before the sync)
        if (kt + NSTAGE - 1 < NK) {
            const int k0 = (kt + NSTAGE - 1) << 5;
            const uint32_t bo = ((kt + NSTAGE - 1) & (NSTAGE - 1)) * BUF_B;
            cp16(sA + bo, gA + k0); cp16(sA + bo + 16, gA + k0 + 8);
            cp16(sB + bo, gB + k0);
        }
        asm volatile("cp.async.commit_group;");

        const uint32_t aBase = sb + (kt & (NSTAGE - 1)) * BUF_B;
#pragma unroll
        for (int kk = 0; kk < 32; kk += 16) {
            const uint32_t kb = kk * 2;
            uint32_t a[2][4], b[4][2];
            ldsm4(a[0][0], a[0][1], a[0][2], a[0][3], aBase + OFF_A + aoff0 + kb);
            ldsm4(a[1][0], a[1][1], a[1][2], a[1][3], aBase + OFF_A + aoff1 + kb);
            ldsm4(b[0][0], b[1][0], b[0][1], b[1][1], aBase + OFF_B + boff0 + kb);
            ldsm4(b[2][0], b[3][0], b[2][1], b[3][1], aBase + OFF_B + boff1 + kb);
#pragma unroll
            for (int mi = 0; mi < 2; mi++)
#pragma unroll
                for (int ni = 0; ni < 4; ni++)
                    mma16816(c[mi][ni][0], c[mi][ni][1], c[mi][ni][2], c[mi][ni][3],
                             a[mi][0], a[mi][1], a[mi][2], a[mi][3],
                             b[ni][0], b[ni][1]);
        }
    }

    // ---------------- epilogue ----------------
#pragma unroll
    for (int ni = 0; ni < 4; ni++) {
        const int col = colBase + warpN + ni * 8 + q * 2;
        const float bv0 = bias[col], bv1 = bias[col + 1];
#pragma unroll
        for (int mi = 0; mi < 2; mi++) {
            const int row0 = rowBase + warpM + mi * 16 + grp;
            float v00 = c[mi][ni][0] + bv0, v01 = c[mi][ni][1] + bv1;
            float v10 = c[mi][ni][2] + bv0, v11 = c[mi][ni][3] + bv1;
            if (ACT == 0) {
                v00 = fmaxf(v00, 0.f); v01 = fmaxf(v01, 0.f);
                v10 = fmaxf(v10, 0.f); v11 = fmaxf(v11, 0.f);
                __half2 H0 = __floats2half2_rn(v00, v01);
                __half2 H1 = __floats2half2_rn(v10, v11);
                *(uint32_t*)(Ch + (size_t)row0 * Mout + col) = *(uint32_t*)&H0;
                *(uint32_t*)(Ch + (size_t)(row0 + 8) * Mout + col) = *(uint32_t*)&H1;
            } else {
                float2 o0 = make_float2(fast_tanh(v00), fast_tanh(v01));
                float2 o1 = make_float2(fast_tanh(v10), fast_tanh(v11));
                *(float2*)(Cf + (size_t)row0 * Mout + col) = o0;
                *(float2*)(Cf + (size_t)(row0 + 8) * Mout + col) = o1;
            }
        }
    }
}

// ---------------- weight rounding (merged: W0, W1, W2 in one launch) ----------------
__global__ void wround_all(const float* __restrict__ W0, const float* __restrict__ W1,
                           const float* __restrict__ W2,
                           __half* __restrict__ h0, __half* __restrict__ h1,
                           __half* __restrict__ h2) {
    int idx = blockIdx.x * blockDim.x + threadIdx.x;
    const int n0 = H_F * E_F, n1 = n0 + H_F * H_F, n2 = n1 + H_F * H_F;
    if (idx < n0)       h0[idx]      = __float2half_rn(W0[idx]);
    else if (idx < n1)  h1[idx - n0] = __float2half_rn(W1[idx - n0]);
    else if (idx < n2)  h2[idx - n1] = __float2half_rn(W2[idx - n1]);
}
// W3: src row e*10+d -> dst row d*128+e ; also permute b3
__global__ void wround_w3(const float* __restrict__ s, __half* __restrict__ h,
                          const float* __restrict__ b3) {
    int idx = blockIdx.x * blockDim.x + threadIdx.x;
    if (idx >= M3 * H_F) return;
    int r = idx >> 9, k = idx & 511;
    int e = r / D_F, d = r - e * D_F;
    h[(size_t)(d * E_F + e) * H_F + k] = __float2half_rn(s[idx]);
    if (idx < M3) {
        int e2 = idx / D_F, d2 = idx - e2 * D_F;
        g_b3p[d2 * E_F + e2] = b3[idx];
    }
}

// ---------------- spline ----------------
__global__ void spline_kernel(const float* __restrict__ t, const float* __restrict__ x) {
    int col = blockIdx.x * blockDim.x + threadIdx.x;
    if (col >= ND) return;
    int n = col / D_F, d = col % D_F;
    float tv[T_K];
#pragma unroll
    for (int i = 0; i < T_K; i++) tv[i] = t[i];
    float xv[T_K];
#pragma unroll
    for (int i = 0; i < T_K; i++) xv[i] = x[(n * T_K + i) * D_F + d];
    float h[T_K - 1];
#pragma unroll
    for (int i = 0; i < T_K - 1; i++) h[i] = tv[i + 1] - tv[i];
    float cp[T_K], dp[T_K];
    cp[0] = 0.f; dp[0] = 0.f;
#pragma unroll
    for (int i = 1; i < T_K - 1; i++) {
        float rhs = 6.f * ((xv[i + 1] - xv[i]) / h[i] - (xv[i] - xv[i - 1]) / h[i - 1]);
        float m = 2.f * (h[i - 1] + h[i]) - h[i - 1] * cp[i - 1];
        float inv = 1.f / m;
        cp[i] = h[i] * inv;
        dp[i] = (rhs - h[i - 1] * dp[i - 1]) * inv;
    }
    float Mv[T_K];
    Mv[T_K - 1] = 0.f;
#pragma unroll
    for (int i = T_K - 2; i >= 0; i--) Mv[i] = dp[i] - cp[i] * Mv[i + 1];
#pragma unroll
    for (int i = 0; i < T_K; i++) g_M[i * ND + col] = Mv[i];
}

// ---------------- dX/dt ----------------
__global__ void dx_kernel(const float* __restrict__ t, const float* __restrict__ x) {
    int idx = blockIdx.x * blockDim.x + threadIdx.x;
    if (idx >= NPTS * ND) return;
    int pt = idx / ND, col = idx - pt * ND;
    int n = col / D_F, d = col - n * D_F;
    int k = pt >> 2, j = pt & 3;
    float t0 = t[k], t1 = t[k + 1];
    float hs = t1 - t0;
    float s;
    if (j == 0) s = t0;
    else if (j == 1) s = t0 + hs / 3.0f;
    else if (j == 2) s = t0 + 2.0f * hs / 3.0f;
    else s = t1;
    int cnt = 0;
#pragma unroll
    for (int i = 0; i < T_K; i++) cnt += (t[i] <= s) ? 1 : 0;
    int i = min(max(cnt - 1, 0), T_K - 2);
    float hi = t[i + 1] - t[i];
    float xi  = x[(n * T_K + i) * D_F + d];
    float xi1 = x[(n * T_K + i + 1) * D_F + d];
    float Mi  = g_M[i * ND + col];
    float Mi1 = g_M[(i + 1) * ND + col];
    float u = s - t[i];
    float b = (xi1 - xi) / hi - hi * (2.0f * Mi + Mi1) / 6.0f;
    g_dX[idx] = b + Mi * u + (Mi1 - Mi) * (u * u) / (2.0f * hi);
}

// ---------------- z0 ----------------
__global__ void z0_kernel(const float* __restrict__ x, const float* __restrict__ We,
                          const float* __restrict__ be) {
    int idx = blockIdx.x * blockDim.x + threadIdx.x;
    if (idx >= NE) return;
    int n = idx / E_F, e = idx - n * E_F;
    float acc = be[e];
#pragma unroll
    for (int d = 0; d < D_F; d++) acc += x[n * T_K * D_F + d] * We[e * D_F + d];
    g_z[idx] = acc;
    g_zh[idx] = __float2half_rn(acc);
}

// ---------------- fused einsum + RK combine (y3 layout [n][d*128+e]) ----------------
__global__ void vf_combine(const float* __restrict__ t, int k, int mode) {
    int idx = blockIdx.x * blockDim.x + threadIdx.x;
    if (idx >= NE) return;
    int n = idx >> 7, e = idx & 127;
    const float* y  = g_y3 + (size_t)n * M3 + e;
    const float* dx = g_dX + (size_t)(k * 4 + mode) * ND + n * D_F;
    float kv = 0.f;
#pragma unroll
    for (int d = 0; d < D_F; d++) kv += y[d * E_F] * dx[d];
    float hs = t[k + 1] - t[k];
    float z = g_z[idx];
    float zn;
    if (mode == 0)      { g_k1[idx] = kv; zn = z + hs * kv / 3.0f; }
    else if (mode == 1) { g_k2[idx] = kv; zn = z + hs * (kv - g_k1[idx] / 3.0f); }
    else if (mode == 2) { g_k3[idx] = kv; zn = z + hs * (g_k1[idx] - g_k2[idx] + kv); }
    else {
        zn = z + hs * (g_k1[idx] + 3.0f * (g_k2[idx] + g_k3[idx]) + kv) / 8.0f;
        g_z[idx] = zn;
    }
    if (mode == 3) g_zh[idx]   = __float2half_rn(zn);
    else           g_zinh[idx] = __float2half_rn(zn);
}

// ---------------- output with mask ----------------
__global__ void out_kernel(const int* __restrict__ mask, float* __restrict__ out) {
    int idx = blockIdx.x * blockDim.x + threadIdx.x;
    if (idx >= NE) return;
    int n = idx / E_F;
    out[idx] = (mask[n] != 0) ? g_z[idx] : 0.0f;
}

// ---------------- launcher ----------------
extern "C" void kernel_launch(void* const* d_in, const int* in_sizes, int n_in,
                              void* d_out, int out_size) {
    const float* t  = (const float*)d_in[0];
    const float* x  = (const float*)d_in[1];
    const int*   mask = (const int*)d_in[2];
    const float* We = (const float*)d_in[3];
    const float* be = (const float*)d_in[4];
    const float* W0 = (const float*)d_in[5];
    const float* b0 = (const float*)d_in[6];
    const float* W1 = (const float*)d_in[7];
    const float* b1 = (const float*)d_in[8];
    const float* W2 = (const float*)d_in[9];
    const float* b2 = (const float*)d_in[10];
    const float* W3 = (const float*)d_in[11];
    const float* b3 = (const float*)d_in[12];

    cudaFuncSetAttribute(mma_gemm<0>, cudaFuncAttributeMaxDynamicSharedMemorySize, SMEM_BYTES);
    cudaFuncSetAttribute(mma_gemm<1>, cudaFuncAttributeMaxDynamicSharedMemorySize, SMEM_BYTES);

    __half *zh, *zinh, *y0, *y1, *y2, *W0r, *W1r, *W2r, *W3r;
    float *y3, *b3p;
    cudaGetSymbolAddress((void**)&zh, g_zh);
    cudaGetSymbolAddress((void**)&zinh, g_zinh);
    cudaGetSymbolAddress((void**)&y0, g_y0);
    cudaGetSymbolAddress((void**)&y1, g_y1);
    cudaGetSymbolAddress((void**)&y2, g_y2);
    cudaGetSymbolAddress((void**)&W0r, g_W0);    cudaGetSymbolAddress((void**)&W1r, g_W1);
    cudaGetSymbolAddress((void**)&W2r, g_W2);    cudaGetSymbolAddress((void**)&W3r, g_W3);
    cudaGetSymbolAddress((void**)&y3, g_y3);
    cudaGetSymbolAddress((void**)&b3p, g_b3p);

    const int nW = H_F * E_F + 2 * H_F * H_F;
    wround_all<<<(nW + 255) / 256, 256>>>(W0, W1, W2, W0r, W1r, W2r);
    wround_w3<<<(M3 * H_F + 255) / 256, 256>>>(W3, W3r, b3);

    spline_kernel<<<(ND + 255) / 256, 256>>>(t, x);
    dx_kernel<<<(NPTS * ND + 255) / 256, 256>>>(t, x);
    z0_kernel<<<(NE + 255) / 256, 256>>>(x, We, be);

    dim3 gH(H_F / 64, N_AG / 128);   // (8, 16)
    dim3 g3(M3 / 64, N_AG / 128);    // (20, 16)
    int eb = (NE + 255) / 256;

    for (int k = 0; k < T_K - 1; k++) {
        for (int stage = 0; stage < 4; stage++) {
            const __half* a0 = (stage == 0) ? zh : zinh;
            mma_gemm<0><<<gH, 256, SMEM_BYTES>>>(a0, W0r, b0, y0, nullptr, E_F, H_F);
            mma_gemm<0><<<gH, 256, SMEM_BYTES>>>(y0, W1r, b1, y1, nullptr, H_F, H_F);
            mma_gemm<0><<<gH, 256, SMEM_BYTES>>>(y1, W2r, b2, y2, nullptr, H_F, H_F);
            mma_gemm<1><<<g3, 256, SMEM_BYTES>>>(y2, W3r, b3p, nullptr, y3, H_F, M3);
            vf_combine<<<eb, 256>>>(t, k, stage);
        }
    }
    out_kernel<<<eb, 256>>>(mask, (float*)d_out);
}

// round 11
// speedup vs baseline: 1.2337x; 1.0667x over previous
#include <cuda_runtime.h>
#include <cuda_fp16.h>
#include <cstdint>

// ---------------- problem constants ----------------
#define N_AG 2048
#define T_K 16
#define D_F 10
#define E_F 128
#define H_F 512
#define M3 (E_F * D_F)      // 1280
#define ND (N_AG * D_F)
#define NPTS 60
#define NE (N_AG * E_F)

// ---------------- scratch ----------------
__device__ float g_M[T_K * ND];
__device__ float g_dX[NPTS * ND];
__device__ float g_z[NE];
__device__ float g_k1[NE];
__device__ float g_k2[NE];
__device__ float g_k3[NE];
__device__ float g_y3[N_AG * M3];     // layout [n][d*128+e]
__device__ float g_b3p[M3];

#define H16A __device__ __align__(16) __half
H16A g_zh[NE];
H16A g_zinh[NE];
H16A g_y0[N_AG * H_F];
H16A g_y1[N_AG * H_F];
H16A g_y2[N_AG * H_F];
H16A g_W0[H_F * E_F];
H16A g_W1[H_F * H_F];
H16A g_W2[H_F * H_F];
H16A g_W3[M3 * H_F];               // rows permuted: dst row = d*128+e

// ---------------- helpers ----------------
__device__ __forceinline__ uint32_t smem_u32(const void* p) {
    uint32_t a;
    asm("{ .reg .u64 t; cvta.to.shared.u64 t, %1; cvt.u32.u64 %0, t; }" : "=r"(a) : "l"(p));
    return a;
}
__device__ __forceinline__ void cp16(uint32_t s, const void* g) {
    asm volatile("cp.async.cg.shared.global [%0], [%1], 16;" :: "r"(s), "l"(g));
}
__device__ __forceinline__ void ldsm4(uint32_t& r0, uint32_t& r1, uint32_t& r2, uint32_t& r3,
                                      uint32_t a) {
    asm volatile("ldmatrix.sync.aligned.m8n8.x4.shared.b16 {%0,%1,%2,%3}, [%4];"
                 : "=r"(r0), "=r"(r1), "=r"(r2), "=r"(r3) : "r"(a));
}
__device__ __forceinline__ void mma16816(float& c0, float& c1, float& c2, float& c3,
                                         uint32_t a0, uint32_t a1, uint32_t a2, uint32_t a3,
                                         uint32_t b0, uint32_t b1) {
    asm volatile("mma.sync.aligned.m16n8k16.row.col.f32.f16.f16.f32 "
                 "{%0,%1,%2,%3},{%4,%5,%6,%7},{%8,%9},{%0,%1,%2,%3};"
                 : "+f"(c0), "+f"(c1), "+f"(c2), "+f"(c3)
                 : "r"(a0), "r"(a1), "r"(a2), "r"(a3), "r"(b0), "r"(b1));
}
__device__ __forceinline__ float fast_tanh(float x) {
    x = fminf(fmaxf(x, -15.f), 15.f);
    float e = __expf(-2.f * x);
    return (1.f - e) * __frcp_rn(1.f + e);
}

// smem per stage buffer: STRIDE 40 halves (80 B rows). A(64 rows) 5120 B, B(64 rows) 5120 B.
#define STRIDE 40
#define OFF_A  0
#define OFF_B  5120
#define BUF_B  10240
#define NSTAGE 4
#define SMEM_BYTES (NSTAGE * BUF_B)      // 40960

// ---------------- fp16 HMMA GEMM, 4-stage cp.async pipeline ----------------
// CTA 64x64, BK=32, 8 warps 4(M)x2(N), warp tile 16x32, ldmatrix feeds.
template <int ACT>  // 0: relu + fp16 out; 1: tanh + fp32 out
__global__ void __launch_bounds__(256) mma_gemm(
    const __half* __restrict__ A, const __half* __restrict__ Bw,
    const float* __restrict__ bias,
    __half* __restrict__ Ch, float* __restrict__ Cf, int K, int Mout)
{
    extern __shared__ char smem[];
    const uint32_t sb = smem_u32(smem);
    const int tid = threadIdx.x, wid = tid >> 5, lid = tid & 31;
    const int rowBase = blockIdx.y * 64;
    const int colBase = blockIdx.x * 64;
    const int warpM = (wid & 3) * 16;
    const int warpN = (wid >> 2) * 32;
    const int grp = lid >> 2, q = lid & 3;

    // cp.async mapping (BK=32): one 16B chunk per thread per array
    const int ar  = tid >> 2;            // row 0..63
    const int acb = (tid & 3) * 8;       // half offset 0/8/16/24

    const __half* gA = A  + (size_t)(rowBase + ar) * K + acb;
    const __half* gB = Bw + (size_t)(colBase + ar) * K + acb;

    const uint32_t sA = sb + OFF_A + (ar * STRIDE + acb) * 2;
    const uint32_t sB = sb + OFF_B + (ar * STRIDE + acb) * 2;

    // ldmatrix lane addressing
    const int sel  = lid >> 3;
    const int lrow = (sel & 1) * 8 + (lid & 7);
    const int lcol = (sel >> 1) * 8;
    const uint32_t aoff  = ((warpM + lrow) * STRIDE + lcol) * 2;
    const uint32_t boff0 = ((warpN + lrow) * STRIDE + lcol) * 2;
    const uint32_t boff1 = ((warpN + 16 + lrow) * STRIDE + lcol) * 2;

    float c[4][4];
#pragma unroll
    for (int ni = 0; ni < 4; ni++)
#pragma unroll
        for (int r = 0; r < 4; r++) c[ni][r] = 0.f;

    const int NK = K >> 5;

    // prologue: stage tiles 0..2
#pragma unroll
    for (int s = 0; s < NSTAGE - 1; s++) {
        if (s < NK) {
            const int k0 = s << 5;
            const uint32_t bo = s * BUF_B;
            cp16(sA + bo, gA + k0);
            cp16(sB + bo, gB + k0);
        }
        asm volatile("cp.async.commit_group;");
    }

    for (int kt = 0; kt < NK; kt++) {
        asm volatile("cp.async.wait_group %0;" :: "n"(NSTAGE - 2));
        __syncthreads();

        if (kt + NSTAGE - 1 < NK) {
            const int k0 = (kt + NSTAGE - 1) << 5;
            const uint32_t bo = ((kt + NSTAGE - 1) & (NSTAGE - 1)) * BUF_B;
            cp16(sA + bo, gA + k0);
            cp16(sB + bo, gB + k0);
        }
        asm volatile("cp.async.commit_group;");

        const uint32_t aBase = sb + (kt & (NSTAGE - 1)) * BUF_B;
#pragma unroll
        for (int kk = 0; kk < 32; kk += 16) {
            const uint32_t kb = kk * 2;
            uint32_t a[4], b[4][2];
            ldsm4(a[0], a[1], a[2], a[3],             aBase + OFF_A + aoff + kb);
            ldsm4(b[0][0], b[1][0], b[0][1], b[1][1], aBase + OFF_B + boff0 + kb);
            ldsm4(b[2][0], b[3][0], b[2][1], b[3][1], aBase + OFF_B + boff1 + kb);
#pragma unroll
            for (int ni = 0; ni < 4; ni++)
                mma16816(c[ni][0], c[ni][1], c[ni][2], c[ni][3],
                         a[0], a[1], a[2], a[3], b[ni][0], b[ni][1]);
        }
    }

    // ---------------- epilogue ----------------
#pragma unroll
    for (int ni = 0; ni < 4; ni++) {
        const int col = colBase + warpN + ni * 8 + q * 2;
        const float bv0 = bias[col], bv1 = bias[col + 1];
        const int row0 = rowBase + warpM + grp;
        float v00 = c[ni][0] + bv0, v01 = c[ni][1] + bv1;
        float v10 = c[ni][2] + bv0, v11 = c[ni][3] + bv1;
        if (ACT == 0) {
            v00 = fmaxf(v00, 0.f); v01 = fmaxf(v01, 0.f);
            v10 = fmaxf(v10, 0.f); v11 = fmaxf(v11, 0.f);
            __half2 H0 = __floats2half2_rn(v00, v01);
            __half2 H1 = __floats2half2_rn(v10, v11);
            *(uint32_t*)(Ch + (size_t)row0 * Mout + col) = *(uint32_t*)&H0;
            *(uint32_t*)(Ch + (size_t)(row0 + 8) * Mout + col) = *(uint32_t*)&H1;
        } else {
            float2 o0 = make_float2(fast_tanh(v00), fast_tanh(v01));
            float2 o1 = make_float2(fast_tanh(v10), fast_tanh(v11));
            *(float2*)(Cf + (size_t)row0 * Mout + col) = o0;
            *(float2*)(Cf + (size_t)(row0 + 8) * Mout + col) = o1;
        }
    }
}

// ---------------- weight rounding (merged: W0, W1, W2 in one launch) ----------------
__global__ void wround_all(const float* __restrict__ W0, const float* __restrict__ W1,
                           const float* __restrict__ W2,
                           __half* __restrict__ h0, __half* __restrict__ h1,
                           __half* __restrict__ h2) {
    int idx = blockIdx.x * blockDim.x + threadIdx.x;
    const int n0 = H_F * E_F, n1 = n0 + H_F * H_F, n2 = n1 + H_F * H_F;
    if (idx < n0)       h0[idx]      = __float2half_rn(W0[idx]);
    else if (idx < n1)  h1[idx - n0] = __float2half_rn(W1[idx - n0]);
    else if (idx < n2)  h2[idx - n1] = __float2half_rn(W2[idx - n1]);
}
// W3: src row e*10+d -> dst row d*128+e ; also permute b3
__global__ void wround_w3(const float* __restrict__ s, __half* __restrict__ h,
                          const float* __restrict__ b3) {
    int idx = blockIdx.x * blockDim.x + threadIdx.x;
    if (idx >= M3 * H_F) return;
    int r = idx >> 9, k = idx & 511;
    int e = r / D_F, d = r - e * D_F;
    h[(size_t)(d * E_F + e) * H_F + k] = __float2half_rn(s[idx]);
    if (idx < M3) {
        int e2 = idx / D_F, d2 = idx - e2 * D_F;
        g_b3p[d2 * E_F + e2] = b3[idx];
    }
}

// ---------------- spline ----------------
__global__ void spline_kernel(const float* __restrict__ t, const float* __restrict__ x) {
    int col = blockIdx.x * blockDim.x + threadIdx.x;
    if (col >= ND) return;
    int n = col / D_F, d = col % D_F;
    float tv[T_K];
#pragma unroll
    for (int i = 0; i < T_K; i++) tv[i] = t[i];
    float xv[T_K];
#pragma unroll
    for (int i = 0; i < T_K; i++) xv[i] = x[(n * T_K + i) * D_F + d];
    float h[T_K - 1];
#pragma unroll
    for (int i = 0; i < T_K - 1; i++) h[i] = tv[i + 1] - tv[i];
    float cp[T_K], dp[T_K];
    cp[0] = 0.f; dp[0] = 0.f;
#pragma unroll
    for (int i = 1; i < T_K - 1; i++) {
        float rhs = 6.f * ((xv[i + 1] - xv[i]) / h[i] - (xv[i] - xv[i - 1]) / h[i - 1]);
        float m = 2.f * (h[i - 1] + h[i]) - h[i - 1] * cp[i - 1];
        float inv = 1.f / m;
        cp[i] = h[i] * inv;
        dp[i] = (rhs - h[i - 1] * dp[i - 1]) * inv;
    }
    float Mv[T_K];
    Mv[T_K - 1] = 0.f;
#pragma unroll
    for (int i = T_K - 2; i >= 0; i--) Mv[i] = dp[i] - cp[i] * Mv[i + 1];
#pragma unroll
    for (int i = 0; i < T_K; i++) g_M[i * ND + col] = Mv[i];
}

// ---------------- dX/dt ----------------
__global__ void dx_kernel(const float* __restrict__ t, const float* __restrict__ x) {
    int idx = blockIdx.x * blockDim.x + threadIdx.x;
    if (idx >= NPTS * ND) return;
    int pt = idx / ND, col = idx - pt * ND;
    int n = col / D_F, d = col - n * D_F;
    int k = pt >> 2, j = pt & 3;
    float t0 = t[k], t1 = t[k + 1];
    float hs = t1 - t0;
    float s;
    if (j == 0) s = t0;
    else if (j == 1) s = t0 + hs / 3.0f;
    else if (j == 2) s = t0 + 2.0f * hs / 3.0f;
    else s = t1;
    int cnt = 0;
#pragma unroll
    for (int i = 0; i < T_K; i++) cnt += (t[i] <= s) ? 1 : 0;
    int i = min(max(cnt - 1, 0), T_K - 2);
    float hi = t[i + 1] - t[i];
    float xi  = x[(n * T_K + i) * D_F + d];
    float xi1 = x[(n * T_K + i + 1) * D_F + d];
    float Mi  = g_M[i * ND + col];
    float Mi1 = g_M[(i + 1) * ND + col];
    float u = s - t[i];
    float b = (xi1 - xi) / hi - hi * (2.0f * Mi + Mi1) / 6.0f;
    g_dX[idx] = b + Mi * u + (Mi1 - Mi) * (u * u) / (2.0f * hi);
}

// ---------------- z0 ----------------
__global__ void z0_kernel(const float* __restrict__ x, const float* __restrict__ We,
                          const float* __restrict__ be) {
    int idx = blockIdx.x * blockDim.x + threadIdx.x;
    if (idx >= NE) return;
    int n = idx / E_F, e = idx - n * E_F;
    float acc = be[e];
#pragma unroll
    for (int d = 0; d < D_F; d++) acc += x[n * T_K * D_F + d] * We[e * D_F + d];
    g_z[idx] = acc;
    g_zh[idx] = __float2half_rn(acc);
}

// ---------------- fused einsum + RK combine (y3 layout [n][d*128+e]) ----------------
__global__ void vf_combine(const float* __restrict__ t, int k, int mode) {
    int idx = blockIdx.x * blockDim.x + threadIdx.x;
    if (idx >= NE) return;
    int n = idx >> 7, e = idx & 127;
    const float* y  = g_y3 + (size_t)n * M3 + e;
    const float* dx = g_dX + (size_t)(k * 4 + mode) * ND + n * D_F;
    float kv = 0.f;
#pragma unroll
    for (int d = 0; d < D_F; d++) kv += y[d * E_F] * dx[d];
    float hs = t[k + 1] - t[k];
    float z = g_z[idx];
    float zn;
    if (mode == 0)      { g_k1[idx] = kv; zn = z + hs * kv / 3.0f; }
    else if (mode == 1) { g_k2[idx] = kv; zn = z + hs * (kv - g_k1[idx] / 3.0f); }
    else if (mode == 2) { g_k3[idx] = kv; zn = z + hs * (g_k1[idx] - g_k2[idx] + kv); }
    else {
        zn = z + hs * (g_k1[idx] + 3.0f * (g_k2[idx] + g_k3[idx]) + kv) / 8.0f;
        g_z[idx] = zn;
    }
    if (mode == 3) g_zh[idx]   = __float2half_rn(zn);
    else           g_zinh[idx] = __float2half_rn(zn);
}

// ---------------- output with mask ----------------
__global__ void out_kernel(const int* __restrict__ mask, float* __restrict__ out) {
    int idx = blockIdx.x * blockDim.x + threadIdx.x;
    if (idx >= NE) return;
    int n = idx / E_F;
    out[idx] = (mask[n] != 0) ? g_z[idx] : 0.0f;
}

// ---------------- launcher ----------------
extern "C" void kernel_launch(void* const* d_in, const int* in_sizes, int n_in,
                              void* d_out, int out_size) {
    const float* t  = (const float*)d_in[0];
    const float* x  = (const float*)d_in[1];
    const int*   mask = (const int*)d_in[2];
    const float* We = (const float*)d_in[3];
    const float* be = (const float*)d_in[4];
    const float* W0 = (const float*)d_in[5];
    const float* b0 = (const float*)d_in[6];
    const float* W1 = (const float*)d_in[7];
    const float* b1 = (const float*)d_in[8];
    const float* W2 = (const float*)d_in[9];
    const float* b2 = (const float*)d_in[10];
    const float* W3 = (const float*)d_in[11];
    const float* b3 = (const float*)d_in[12];

    cudaFuncSetAttribute(mma_gemm<0>, cudaFuncAttributeMaxDynamicSharedMemorySize, SMEM_BYTES);
    cudaFuncSetAttribute(mma_gemm<1>, cudaFuncAttributeMaxDynamicSharedMemorySize, SMEM_BYTES);

    __half *zh, *zinh, *y0, *y1, *y2, *W0r, *W1r, *W2r, *W3r;
    float *y3, *b3p;
    cudaGetSymbolAddress((void**)&zh, g_zh);
    cudaGetSymbolAddress((void**)&zinh, g_zinh);
    cudaGetSymbolAddress((void**)&y0, g_y0);
    cudaGetSymbolAddress((void**)&y1, g_y1);
    cudaGetSymbolAddress((void**)&y2, g_y2);
    cudaGetSymbolAddress((void**)&W0r, g_W0);    cudaGetSymbolAddress((void**)&W1r, g_W1);
    cudaGetSymbolAddress((void**)&W2r, g_W2);    cudaGetSymbolAddress((void**)&W3r, g_W3);
    cudaGetSymbolAddress((void**)&y3, g_y3);
    cudaGetSymbolAddress((void**)&b3p, g_b3p);

    const int nW = H_F * E_F + 2 * H_F * H_F;
    wround_all<<<(nW + 255) / 256, 256>>>(W0, W1, W2, W0r, W1r, W2r);
    wround_w3<<<(M3 * H_F + 255) / 256, 256>>>(W3, W3r, b3);

    spline_kernel<<<(ND + 255) / 256, 256>>>(t, x);
    dx_kernel<<<(NPTS * ND + 255) / 256, 256>>>(t, x);
    z0_kernel<<<(NE + 255) / 256, 256>>>(x, We, be);

    dim3 gH(H_F / 64, N_AG / 64);   // (8, 32) = 256 CTAs
    dim3 g3(M3 / 64, N_AG / 64);    // (20, 32) = 640 CTAs
    int eb = (NE + 255) / 256;

    for (int k = 0; k < T_K - 1; k++) {
        for (int stage = 0; stage < 4; stage++) {
            const __half* a0 = (stage == 0) ? zh : zinh;
            mma_gemm<0><<<gH, 256, SMEM_BYTES>>>(a0, W0r, b0, y0, nullptr, E_F, H_F);
            mma_gemm<0><<<gH, 256, SMEM_BYTES>>>(y0, W1r, b1, y1, nullptr, H_F, H_F);
            mma_gemm<0><<<gH, 256, SMEM_BYTES>>>(y1, W2r, b2, y2, nullptr, H_F, H_F);
            mma_gemm<1><<<g3, 256, SMEM_BYTES>>>(y2, W3r, b3p, nullptr, y3, H_F, M3);
            vf_combine<<<eb, 256>>>(t, k, stage);
        }
    }
    out_kernel<<<eb, 256>>>(mask, (float*)d_out);
}